// round 8
// baseline (speedup 1.0000x reference)
#include <cuda_runtime.h>
#include <cuda_fp16.h>
#include <stdint.h>

#define NUM_SEGMENTS 4480
#define ATOM_DIM 64
#define BOND_DIM 16
#define N_EDGES 65536
#define NCOLS 1088   // 16*64 kernel-projected cols + 64 bias cols
#define CAP 128      // max edges per src bucket (lambda=14.6; overflow prob ~0)

// Scratch
__device__ __half g_Yh[(size_t)NUM_SEGMENTS * NCOLS];
__device__ int    g_cursor[NUM_SEGMENTS];
__device__ int    g_pk[NUM_SEGMENTS * CAP];   // (dst<<16) | eid

// ---- tensor-core helpers ----
__device__ __forceinline__ uint32_t smem_u32(const void* p) {
    return (uint32_t)__cvta_generic_to_shared(p);
}
__device__ __forceinline__ void ldm_x4(uint32_t& r0, uint32_t& r1,
                                       uint32_t& r2, uint32_t& r3, uint32_t addr) {
    asm volatile("ldmatrix.sync.aligned.m8n8.x4.shared.b16 {%0,%1,%2,%3}, [%4];"
                 : "=r"(r0), "=r"(r1), "=r"(r2), "=r"(r3) : "r"(addr));
}
__device__ __forceinline__ void mma16816(float* c,
                                         uint32_t a0, uint32_t a1, uint32_t a2, uint32_t a3,
                                         uint32_t b0, uint32_t b1) {
    asm volatile("mma.sync.aligned.m16n8k16.row.col.f32.f16.f16.f32 "
                 "{%0,%1,%2,%3}, {%4,%5,%6,%7}, {%8,%9}, {%0,%1,%2,%3};"
                 : "+f"(c[0]), "+f"(c[1]), "+f"(c[2]), "+f"(c[3])
                 : "r"(a0), "r"(a1), "r"(a2), "r"(a3), "r"(b0), "r"(b1));
}

#define AH_STRIDE 72
#define BS_STRIDE 72

// ---------------------------------------------------------------------------
// Phase 1 (tensor cores): Y = atom (4480x64) @ W (64x1088) -> fp16.
// Identical MMA structure to R7 (validated); prologue fills vectorized.
// blockIdx.y==0: zero `out`.  blockIdx.y==1: zero g_cursor.
// ---------------------------------------------------------------------------
__global__ void __launch_bounds__(256)
proj_kernel(const float* __restrict__ atom,
            const float* __restrict__ kern,
            const float* __restrict__ bias,
            float* __restrict__ out)
{
    __shared__ __align__(16) __half Ah[128 * AH_STRIDE];
    __shared__ __align__(16) __half Bs[64 * BS_STRIDE];

    const int a0  = blockIdx.x * 128;  // 35 blocks
    const int c0g = blockIdx.y * 64;   // 17 blocks
    const int tid = threadIdx.x;

    if (blockIdx.y == 0) {
        float4* oz = (float4*)(out + (size_t)a0 * 64);
        #pragma unroll
        for (int t = 0; t < 8; t++)
            oz[tid + t * 256] = make_float4(0.f, 0.f, 0.f, 0.f);
    } else if (blockIdx.y == 1) {
        int i = blockIdx.x * 256 + tid;        // 35*256 = 8960 >= 4480
        if (i < NUM_SEGMENTS) g_cursor[i] = 0;
    }

    // Fill Ah[r][j] from atom via float4 (8 iters/thread)
    #pragma unroll
    for (int t = 0; t < 8; t++) {
        int idx = tid + t * 256;          // 2048 float4s: r = idx/16, f4 = idx%16
        int r = idx >> 4, f4 = idx & 15;
        float4 v = *(const float4*)(atom + (size_t)(a0 + r) * 64 + f4 * 4);
        __half2 h01 = __floats2half2_rn(v.x, v.y);
        __half2 h23 = __floats2half2_rn(v.z, v.w);
        *(uint2*)&Ah[r * AH_STRIDE + f4 * 4] =
            make_uint2(*(uint32_t*)&h01, *(uint32_t*)&h23);
    }
    // Fill Bs[c][j] = W[j][c0g+c] via float4 (4 iters/thread)
    #pragma unroll
    for (int t = 0; t < 4; t++) {
        int idx = tid + t * 256;          // 1024 float4s: c = idx/16, f4 = idx%16
        int c = idx >> 4, f4 = idx & 15;
        int gc = c0g + c;
        const float* wsrc;
        if (gc < 1024) { int kk = gc >> 6, i = gc & 63; wsrc = kern + kk * 4096 + i * 64; }
        else           { wsrc = bias + (gc - 1024) * 64; }
        float4 v = *(const float4*)(wsrc + f4 * 4);
        __half2 h01 = __floats2half2_rn(v.x, v.y);
        __half2 h23 = __floats2half2_rn(v.z, v.w);
        *(uint2*)&Bs[c * BS_STRIDE + f4 * 4] =
            make_uint2(*(uint32_t*)&h01, *(uint32_t*)&h23);
    }
    __syncthreads();

    const int wid  = tid >> 5;
    const int lane = tid & 31;
    const int m0   = wid * 16;

    float acc[8][4] = {};

    const uint32_t a_base =
        smem_u32(&Ah[(m0 + (lane & 15)) * AH_STRIDE + ((lane >> 4) << 3)]);
    const uint32_t b_base =
        smem_u32(&Bs[(((lane >> 4) << 3) + (lane & 7)) * BS_STRIDE +
                     (((lane >> 3) & 1) << 3)]);

    #pragma unroll
    for (int ks = 0; ks < 4; ks++) {
        uint32_t A0, A1, A2, A3;
        ldm_x4(A0, A1, A2, A3, a_base + ks * 32);
        #pragma unroll
        for (int nss = 0; nss < 4; nss++) {
            uint32_t B0, B1, B2, B3;
            ldm_x4(B0, B1, B2, B3,
                   b_base + nss * 16 * BS_STRIDE * 2 + ks * 32);
            mma16816(acc[2 * nss],     A0, A1, A2, A3, B0, B1);
            mma16816(acc[2 * nss + 1], A0, A1, A2, A3, B2, B3);
        }
    }

    const int r  = lane >> 2;
    const int cp = (lane & 3) * 2;
    #pragma unroll
    for (int s = 0; s < 8; s++) {
        const int col = c0g + s * 8 + cp;
        const size_t row0 = (size_t)(a0 + m0 + r);
        *(__half2*)&g_Yh[row0 * NCOLS + col]       = __floats2half2_rn(acc[s][0], acc[s][1]);
        *(__half2*)&g_Yh[(row0 + 8) * NCOLS + col] = __floats2half2_rn(acc[s][2], acc[s][3]);
    }
}

// ---------------------------------------------------------------------------
// Phase 2a: bucket edges by src. pos = atomicAdd(cursor[src]); pk = (dst<<16)|eid.
// 2 edges/thread for atomic MLP. Requires g_cursor zeroed (done in proj).
// ---------------------------------------------------------------------------
__global__ void __launch_bounds__(256)
scatter_kernel(const int* __restrict__ pair)
{
    const int t = blockIdx.x * 256 + threadIdx.x;   // 32768 threads
    const int2 p0 = ((const int2*)pair)[t];
    const int2 p1 = ((const int2*)pair)[t + 32768];
    const int pos0 = atomicAdd(&g_cursor[p0.y], 1);
    const int pos1 = atomicAdd(&g_cursor[p1.y], 1);
    if (pos0 < CAP) g_pk[p0.y * CAP + pos0] = (p0.x << 16) | t;
    if (pos1 < CAP) g_pk[p1.y * CAP + pos1] = (p1.x << 16) | (t + 32768);
}

// ---------------------------------------------------------------------------
// Phase 2b: one warp per src atom. Y[src] -> registers once; stream edges.
// Lane handles output cols (lane, lane+32).
// ---------------------------------------------------------------------------
__global__ void __launch_bounds__(256)
gather_kernel(const float* __restrict__ bond,
              float* __restrict__ out)
{
    const int a = blockIdx.x * 8 + (threadIdx.x >> 5);   // 560 blocks * 8 warps = 4480
    const int lane = threadIdx.x & 31;

    int deg = g_cursor[a];
    if (deg <= 0) return;
    if (deg > CAP) deg = CAP;

    const __half* __restrict__ y = g_Yh + (size_t)a * NCOLS;
    float yk0[16], yk1[16];
    #pragma unroll
    for (int k = 0; k < 16; k++) {
        yk0[k] = __half2float(y[k * 64 + lane]);
        yk1[k] = __half2float(y[k * 64 + 32 + lane]);
    }
    const float b0 = __half2float(y[1024 + lane]);
    const float b1 = __half2float(y[1024 + 32 + lane]);

    const int base = a * CAP;
    for (int j0 = 0; j0 < deg; j0 += 32) {
        const int n = min(32, deg - j0);
        int pk_l = 0;
        if (lane < n) pk_l = g_pk[base + j0 + lane];

        for (int j = 0; j < n; j++) {
            const int pk  = __shfl_sync(0xffffffffu, pk_l, j);
            const int eid = pk & 0xffff;
            const int dst = pk >> 16;

            const float4* __restrict__ bp = (const float4*)(bond + (size_t)eid * 16);
            const float4 q0 = __ldg(bp + 0);
            const float4 q1 = __ldg(bp + 1);
            const float4 q2 = __ldg(bp + 2);
            const float4 q3 = __ldg(bp + 3);

            float m0 = b0, m1 = b1;
            m0 = fmaf(q0.x, yk0[0],  m0);  m1 = fmaf(q0.x, yk1[0],  m1);
            m0 = fmaf(q0.y, yk0[1],  m0);  m1 = fmaf(q0.y, yk1[1],  m1);
            m0 = fmaf(q0.z, yk0[2],  m0);  m1 = fmaf(q0.z, yk1[2],  m1);
            m0 = fmaf(q0.w, yk0[3],  m0);  m1 = fmaf(q0.w, yk1[3],  m1);
            m0 = fmaf(q1.x, yk0[4],  m0);  m1 = fmaf(q1.x, yk1[4],  m1);
            m0 = fmaf(q1.y, yk0[5],  m0);  m1 = fmaf(q1.y, yk1[5],  m1);
            m0 = fmaf(q1.z, yk0[6],  m0);  m1 = fmaf(q1.z, yk1[6],  m1);
            m0 = fmaf(q1.w, yk0[7],  m0);  m1 = fmaf(q1.w, yk1[7],  m1);
            m0 = fmaf(q2.x, yk0[8],  m0);  m1 = fmaf(q2.x, yk1[8],  m1);
            m0 = fmaf(q2.y, yk0[9],  m0);  m1 = fmaf(q2.y, yk1[9],  m1);
            m0 = fmaf(q2.z, yk0[10], m0);  m1 = fmaf(q2.z, yk1[10], m1);
            m0 = fmaf(q2.w, yk0[11], m0);  m1 = fmaf(q2.w, yk1[11], m1);
            m0 = fmaf(q3.x, yk0[12], m0);  m1 = fmaf(q3.x, yk1[12], m1);
            m0 = fmaf(q3.y, yk0[13], m0);  m1 = fmaf(q3.y, yk1[13], m1);
            m0 = fmaf(q3.z, yk0[14], m0);  m1 = fmaf(q3.z, yk1[14], m1);
            m0 = fmaf(q3.w, yk0[15], m0);  m1 = fmaf(q3.w, yk1[15], m1);

            float* o = out + (size_t)dst * 64 + lane;
            atomicAdd(o,      m0);
            atomicAdd(o + 32, m1);
        }
    }
}

extern "C" void kernel_launch(void* const* d_in, const int* in_sizes, int n_in,
                              void* d_out, int out_size)
{
    const float* atom = (const float*)d_in[0];      // [4480, 64]
    const float* bond = (const float*)d_in[1];      // [65536, 16]
    const int*   pair = (const int*)d_in[2];        // [65536, 2] int32
    const float* kern = (const float*)d_in[3];      // [16, 4096]
    const float* bias = (const float*)d_in[4];      // [4096]
    float*       out  = (float*)d_out;              // [4480, 64]

    (void)in_sizes; (void)n_in; (void)out_size;

    dim3 grid1(NUM_SEGMENTS / 128, 17);  // (35, 17); y==0 zeroes out, y==1 zeroes cursors
    proj_kernel<<<grid1, 256>>>(atom, kern, bias, out);

    scatter_kernel<<<128, 256>>>(pair);

    gather_kernel<<<NUM_SEGMENTS / 8, 256>>>(bond, out);
}

// round 9
// speedup vs baseline: 1.1592x; 1.1592x over previous
#include <cuda_runtime.h>
#include <cuda_fp16.h>
#include <stdint.h>

#define NUM_SEGMENTS 4480
#define ATOM_DIM 64
#define BOND_DIM 16
#define N_EDGES 65536
#define NCOLS 1088   // 16*64 kernel-projected cols + 64 bias cols
#define CAP 128      // max edges per src bucket (lambda=14.6; overflow prob ~0)

// Scratch
__device__ __half g_Yh[(size_t)NUM_SEGMENTS * NCOLS];
__device__ int    g_cursor[NUM_SEGMENTS];
__device__ int    g_pk[NUM_SEGMENTS * CAP];   // (dst<<16) | eid

// ---- tensor-core helpers ----
__device__ __forceinline__ uint32_t smem_u32(const void* p) {
    return (uint32_t)__cvta_generic_to_shared(p);
}
__device__ __forceinline__ void ldm_x4(uint32_t& r0, uint32_t& r1,
                                       uint32_t& r2, uint32_t& r3, uint32_t addr) {
    asm volatile("ldmatrix.sync.aligned.m8n8.x4.shared.b16 {%0,%1,%2,%3}, [%4];"
                 : "=r"(r0), "=r"(r1), "=r"(r2), "=r"(r3) : "r"(addr));
}
__device__ __forceinline__ void mma16816(float* c,
                                         uint32_t a0, uint32_t a1, uint32_t a2, uint32_t a3,
                                         uint32_t b0, uint32_t b1) {
    asm volatile("mma.sync.aligned.m16n8k16.row.col.f32.f16.f16.f32 "
                 "{%0,%1,%2,%3}, {%4,%5,%6,%7}, {%8,%9}, {%0,%1,%2,%3};"
                 : "+f"(c[0]), "+f"(c[1]), "+f"(c[2]), "+f"(c[3])
                 : "r"(a0), "r"(a1), "r"(a2), "r"(a3), "r"(b0), "r"(b1));
}

#define AH_STRIDE 72
#define BS_STRIDE 72

// ---------------------------------------------------------------------------
// Phase 1 (tensor cores): Y = atom (4480x64) @ W (64x1088) -> fp16.
// Validated in R7/R8. blockIdx.y==0: zero `out`. blockIdx.y==1: zero g_cursor.
// ---------------------------------------------------------------------------
__global__ void __launch_bounds__(256)
proj_kernel(const float* __restrict__ atom,
            const float* __restrict__ kern,
            const float* __restrict__ bias,
            float* __restrict__ out)
{
    __shared__ __align__(16) __half Ah[128 * AH_STRIDE];
    __shared__ __align__(16) __half Bs[64 * BS_STRIDE];

    const int a0  = blockIdx.x * 128;  // 35 blocks
    const int c0g = blockIdx.y * 64;   // 17 blocks
    const int tid = threadIdx.x;

    if (blockIdx.y == 0) {
        float4* oz = (float4*)(out + (size_t)a0 * 64);
        #pragma unroll
        for (int t = 0; t < 8; t++)
            oz[tid + t * 256] = make_float4(0.f, 0.f, 0.f, 0.f);
    } else if (blockIdx.y == 1) {
        int i = blockIdx.x * 256 + tid;        // 35*256 = 8960 >= 4480
        if (i < NUM_SEGMENTS) g_cursor[i] = 0;
    }

    #pragma unroll
    for (int t = 0; t < 8; t++) {
        int idx = tid + t * 256;
        int r = idx >> 4, f4 = idx & 15;
        float4 v = *(const float4*)(atom + (size_t)(a0 + r) * 64 + f4 * 4);
        __half2 h01 = __floats2half2_rn(v.x, v.y);
        __half2 h23 = __floats2half2_rn(v.z, v.w);
        *(uint2*)&Ah[r * AH_STRIDE + f4 * 4] =
            make_uint2(*(uint32_t*)&h01, *(uint32_t*)&h23);
    }
    #pragma unroll
    for (int t = 0; t < 4; t++) {
        int idx = tid + t * 256;
        int c = idx >> 4, f4 = idx & 15;
        int gc = c0g + c;
        const float* wsrc;
        if (gc < 1024) { int kk = gc >> 6, i = gc & 63; wsrc = kern + kk * 4096 + i * 64; }
        else           { wsrc = bias + (gc - 1024) * 64; }
        float4 v = *(const float4*)(wsrc + f4 * 4);
        __half2 h01 = __floats2half2_rn(v.x, v.y);
        __half2 h23 = __floats2half2_rn(v.z, v.w);
        *(uint2*)&Bs[c * BS_STRIDE + f4 * 4] =
            make_uint2(*(uint32_t*)&h01, *(uint32_t*)&h23);
    }
    __syncthreads();

    const int wid  = tid >> 5;
    const int lane = tid & 31;
    const int m0   = wid * 16;

    float acc[8][4] = {};

    const uint32_t a_base =
        smem_u32(&Ah[(m0 + (lane & 15)) * AH_STRIDE + ((lane >> 4) << 3)]);
    const uint32_t b_base =
        smem_u32(&Bs[(((lane >> 4) << 3) + (lane & 7)) * BS_STRIDE +
                     (((lane >> 3) & 1) << 3)]);

    #pragma unroll
    for (int ks = 0; ks < 4; ks++) {
        uint32_t A0, A1, A2, A3;
        ldm_x4(A0, A1, A2, A3, a_base + ks * 32);
        #pragma unroll
        for (int nss = 0; nss < 4; nss++) {
            uint32_t B0, B1, B2, B3;
            ldm_x4(B0, B1, B2, B3,
                   b_base + nss * 16 * BS_STRIDE * 2 + ks * 32);
            mma16816(acc[2 * nss],     A0, A1, A2, A3, B0, B1);
            mma16816(acc[2 * nss + 1], A0, A1, A2, A3, B2, B3);
        }
    }

    const int r  = lane >> 2;
    const int cp = (lane & 3) * 2;
    #pragma unroll
    for (int s = 0; s < 8; s++) {
        const int col = c0g + s * 8 + cp;
        const size_t row0 = (size_t)(a0 + m0 + r);
        *(__half2*)&g_Yh[row0 * NCOLS + col]       = __floats2half2_rn(acc[s][0], acc[s][1]);
        *(__half2*)&g_Yh[(row0 + 8) * NCOLS + col] = __floats2half2_rn(acc[s][2], acc[s][3]);
    }
}

// ---------------------------------------------------------------------------
// Phase 2a: bucket edges by src, 4 edges/thread for atomic MLP.
// ---------------------------------------------------------------------------
__global__ void __launch_bounds__(256)
scatter_kernel(const int* __restrict__ pair)
{
    const int t = blockIdx.x * 256 + threadIdx.x;   // 16384 threads
    const int2 p0 = ((const int2*)pair)[t];
    const int2 p1 = ((const int2*)pair)[t + 16384];
    const int2 p2 = ((const int2*)pair)[t + 32768];
    const int2 p3 = ((const int2*)pair)[t + 49152];
    const int pos0 = atomicAdd(&g_cursor[p0.y], 1);
    const int pos1 = atomicAdd(&g_cursor[p1.y], 1);
    const int pos2 = atomicAdd(&g_cursor[p2.y], 1);
    const int pos3 = atomicAdd(&g_cursor[p3.y], 1);
    if (pos0 < CAP) g_pk[p0.y * CAP + pos0] = (p0.x << 16) | t;
    if (pos1 < CAP) g_pk[p1.y * CAP + pos1] = (p1.x << 16) | (t + 16384);
    if (pos2 < CAP) g_pk[p2.y * CAP + pos2] = (p2.x << 16) | (t + 32768);
    if (pos3 < CAP) g_pk[p3.y * CAP + pos3] = (p3.x << 16) | (t + 49152);
}

// ---------------------------------------------------------------------------
// Phase 2b: one warp per src atom. Lane owns cols {2*lane, 2*lane+1}.
// Y[src] -> 17 float2 in regs (one half2 load each). Edge loop unrolled x2.
// Message written with one red.global.add.v2.f32 per edge per lane.
// ---------------------------------------------------------------------------
__global__ void __launch_bounds__(256)
gather_kernel(const float* __restrict__ bond,
              float* __restrict__ out)
{
    const int a = blockIdx.x * 8 + (threadIdx.x >> 5);   // 560 blocks * 8 warps
    const int lane = threadIdx.x & 31;

    int deg = g_cursor[a];
    if (deg <= 0) return;
    if (deg > CAP) deg = CAP;

    const __half* __restrict__ y = g_Yh + (size_t)a * NCOLS + 2 * lane;
    float2 yk[16];
    #pragma unroll
    for (int k = 0; k < 16; k++)
        yk[k] = __half22float2(*(const __half2*)(y + k * 64));
    const float2 bb = __half22float2(*(const __half2*)(y + 1024));

    const float4* __restrict__ bond4 = (const float4*)bond;
    const int base = a * CAP;

    for (int j0 = 0; j0 < deg; j0 += 32) {
        const int n = min(32, deg - j0);
        int pk_l = 0;
        if (lane < n) pk_l = g_pk[base + j0 + lane];

        int j = 0;
        for (; j + 2 <= n; j += 2) {
            const int pkA = __shfl_sync(0xffffffffu, pk_l, j);
            const int pkB = __shfl_sync(0xffffffffu, pk_l, j + 1);
            const float4* bpA = bond4 + (size_t)(pkA & 0xffff) * 4;
            const float4* bpB = bond4 + (size_t)(pkB & 0xffff) * 4;
            const float4 qA0 = __ldg(bpA + 0), qA1 = __ldg(bpA + 1);
            const float4 qA2 = __ldg(bpA + 2), qA3 = __ldg(bpA + 3);
            const float4 qB0 = __ldg(bpB + 0), qB1 = __ldg(bpB + 1);
            const float4 qB2 = __ldg(bpB + 2), qB3 = __ldg(bpB + 3);

            float a0 = bb.x, a1 = bb.y;
            float b0 = bb.x, b1 = bb.y;
            const float cA[16] = {qA0.x,qA0.y,qA0.z,qA0.w, qA1.x,qA1.y,qA1.z,qA1.w,
                                  qA2.x,qA2.y,qA2.z,qA2.w, qA3.x,qA3.y,qA3.z,qA3.w};
            const float cB[16] = {qB0.x,qB0.y,qB0.z,qB0.w, qB1.x,qB1.y,qB1.z,qB1.w,
                                  qB2.x,qB2.y,qB2.z,qB2.w, qB3.x,qB3.y,qB3.z,qB3.w};
            #pragma unroll
            for (int k = 0; k < 16; k++) {
                a0 = fmaf(cA[k], yk[k].x, a0);
                a1 = fmaf(cA[k], yk[k].y, a1);
                b0 = fmaf(cB[k], yk[k].x, b0);
                b1 = fmaf(cB[k], yk[k].y, b1);
            }
            float* oA = out + (size_t)(pkA >> 16) * 64 + 2 * lane;
            float* oB = out + (size_t)(pkB >> 16) * 64 + 2 * lane;
            asm volatile("red.global.add.v2.f32 [%0], {%1, %2};"
                         :: "l"(oA), "f"(a0), "f"(a1) : "memory");
            asm volatile("red.global.add.v2.f32 [%0], {%1, %2};"
                         :: "l"(oB), "f"(b0), "f"(b1) : "memory");
        }
        if (j < n) {
            const int pkA = __shfl_sync(0xffffffffu, pk_l, j);
            const float4* bpA = bond4 + (size_t)(pkA & 0xffff) * 4;
            const float4 qA0 = __ldg(bpA + 0), qA1 = __ldg(bpA + 1);
            const float4 qA2 = __ldg(bpA + 2), qA3 = __ldg(bpA + 3);
            float a0 = bb.x, a1 = bb.y;
            const float cA[16] = {qA0.x,qA0.y,qA0.z,qA0.w, qA1.x,qA1.y,qA1.z,qA1.w,
                                  qA2.x,qA2.y,qA2.z,qA2.w, qA3.x,qA3.y,qA3.z,qA3.w};
            #pragma unroll
            for (int k = 0; k < 16; k++) {
                a0 = fmaf(cA[k], yk[k].x, a0);
                a1 = fmaf(cA[k], yk[k].y, a1);
            }
            float* oA = out + (size_t)(pkA >> 16) * 64 + 2 * lane;
            asm volatile("red.global.add.v2.f32 [%0], {%1, %2};"
                         :: "l"(oA), "f"(a0), "f"(a1) : "memory");
        }
    }
}

extern "C" void kernel_launch(void* const* d_in, const int* in_sizes, int n_in,
                              void* d_out, int out_size)
{
    const float* atom = (const float*)d_in[0];      // [4480, 64]
    const float* bond = (const float*)d_in[1];      // [65536, 16]
    const int*   pair = (const int*)d_in[2];        // [65536, 2] int32
    const float* kern = (const float*)d_in[3];      // [16, 4096]
    const float* bias = (const float*)d_in[4];      // [4096]
    float*       out  = (float*)d_out;              // [4480, 64]

    (void)in_sizes; (void)n_in; (void)out_size;

    dim3 grid1(NUM_SEGMENTS / 128, 17);  // (35, 17); y==0 zeroes out, y==1 zeroes cursors
    proj_kernel<<<grid1, 256>>>(atom, kern, bias, out);

    scatter_kernel<<<64, 256>>>(pair);

    gather_kernel<<<NUM_SEGMENTS / 8, 256>>>(bond, out);
}

// round 10
// speedup vs baseline: 1.3503x; 1.1648x over previous
#include <cuda_runtime.h>
#include <cuda_fp16.h>
#include <stdint.h>

#define NUM_SEGMENTS 4480
#define ATOM_DIM 64
#define BOND_DIM 16
#define N_EDGES 65536
#define YSTRIDE 1152   // padded row stride (halves): 1024 kernel cols + 64 bias + 64 pad

// Scratch: per-atom projected features in fp16, padded stride.
__device__ __half g_Yh[(size_t)NUM_SEGMENTS * YSTRIDE];

// ---- tensor-core helpers ----
__device__ __forceinline__ uint32_t smem_u32(const void* p) {
    return (uint32_t)__cvta_generic_to_shared(p);
}
__device__ __forceinline__ void ldm_x4(uint32_t& r0, uint32_t& r1,
                                       uint32_t& r2, uint32_t& r3, uint32_t addr) {
    asm volatile("ldmatrix.sync.aligned.m8n8.x4.shared.b16 {%0,%1,%2,%3}, [%4];"
                 : "=r"(r0), "=r"(r1), "=r"(r2), "=r"(r3) : "r"(addr));
}
__device__ __forceinline__ void mma16816(float* c,
                                         uint32_t a0, uint32_t a1, uint32_t a2, uint32_t a3,
                                         uint32_t b0, uint32_t b1) {
    asm volatile("mma.sync.aligned.m16n8k16.row.col.f32.f16.f16.f32 "
                 "{%0,%1,%2,%3}, {%4,%5,%6,%7}, {%8,%9}, {%0,%1,%2,%3};"
                 : "+f"(c[0]), "+f"(c[1]), "+f"(c[2]), "+f"(c[3])
                 : "r"(a0), "r"(a1), "r"(a2), "r"(a3), "r"(b0), "r"(b1));
}

#define AH_STRIDE 72
#define BS_STRIDE 72

// ---------------------------------------------------------------------------
// Phase 1 (tensor cores): Y = atom (4480x64) @ W (64x1088) -> fp16 (stride 1152).
//   W[j][c] = kernel[(c>>6)*4096 + (c&63)*64 + j]  (c<1024)
//   W[j][1024+i] = bias[i*64 + j];  W[j][c>=1088] = 0 (stored to padding)
// Block tile 128(M) x 128(N) processed as two 64-col halves sharing the A tile
// and hoisted A fragments. Grid (35, 9). y==0 blocks also zero `out`.
// ---------------------------------------------------------------------------
__global__ void __launch_bounds__(256)
proj_kernel(const float* __restrict__ atom,
            const float* __restrict__ kern,
            const float* __restrict__ bias,
            float* __restrict__ out)
{
    __shared__ __align__(16) __half Ah[128 * AH_STRIDE];   // 18 KB
    __shared__ __align__(16) __half Bs[128 * BS_STRIDE];   // 18 KB (128 cols)

    const int a0  = blockIdx.x * 128;   // 35 blocks
    const int c0g = blockIdx.y * 128;   // 9 blocks (last: 1024..1151, tail padded)
    const int tid = threadIdx.x;

    if (blockIdx.y == 0) {
        float4* oz = (float4*)(out + (size_t)a0 * 64);
        #pragma unroll
        for (int t = 0; t < 8; t++)
            oz[tid + t * 256] = make_float4(0.f, 0.f, 0.f, 0.f);
    }

    // Fill Ah[r][j] from atom via float4 (8 iters)
    #pragma unroll
    for (int t = 0; t < 8; t++) {
        int idx = tid + t * 256;
        int r = idx >> 4, f4 = idx & 15;
        float4 v = *(const float4*)(atom + (size_t)(a0 + r) * 64 + f4 * 4);
        __half2 h01 = __floats2half2_rn(v.x, v.y);
        __half2 h23 = __floats2half2_rn(v.z, v.w);
        *(uint2*)&Ah[r * AH_STRIDE + f4 * 4] =
            make_uint2(*(uint32_t*)&h01, *(uint32_t*)&h23);
    }
    // Fill Bs[c][j] = W[j][c0g+c] for c in 0..127 via float4 (8 iters)
    #pragma unroll
    for (int t = 0; t < 8; t++) {
        int idx = tid + t * 256;          // 2048 float4s: c = idx/16, f4 = idx%16
        int c = idx >> 4, f4 = idx & 15;
        int gc = c0g + c;
        float4 v = make_float4(0.f, 0.f, 0.f, 0.f);
        if (gc < 1024) {
            int kk = gc >> 6, i = gc & 63;
            v = *(const float4*)(kern + kk * 4096 + i * 64 + f4 * 4);
        } else if (gc < 1088) {
            v = *(const float4*)(bias + (gc - 1024) * 64 + f4 * 4);
        }
        __half2 h01 = __floats2half2_rn(v.x, v.y);
        __half2 h23 = __floats2half2_rn(v.z, v.w);
        *(uint2*)&Bs[c * BS_STRIDE + f4 * 4] =
            make_uint2(*(uint32_t*)&h01, *(uint32_t*)&h23);
    }
    __syncthreads();

    const int wid  = tid >> 5;
    const int lane = tid & 31;
    const int m0   = wid * 16;

    // Hoisted A fragments (shared by both c-halves)
    uint32_t Af[4][4];
    {
        const uint32_t a_base =
            smem_u32(&Ah[(m0 + (lane & 15)) * AH_STRIDE + ((lane >> 4) << 3)]);
        #pragma unroll
        for (int ks = 0; ks < 4; ks++)
            ldm_x4(Af[ks][0], Af[ks][1], Af[ks][2], Af[ks][3], a_base + ks * 32);
    }

    const int r  = lane >> 2;
    const int cp = (lane & 3) * 2;

    #pragma unroll
    for (int h = 0; h < 2; h++) {
        const uint32_t b_base =
            smem_u32(&Bs[(h * 64 + ((lane >> 4) << 3) + (lane & 7)) * BS_STRIDE +
                         (((lane >> 3) & 1) << 3)]);

        float acc[8][4] = {};
        #pragma unroll
        for (int ks = 0; ks < 4; ks++) {
            #pragma unroll
            for (int nss = 0; nss < 4; nss++) {
                uint32_t B0, B1, B2, B3;
                ldm_x4(B0, B1, B2, B3,
                       b_base + nss * 16 * BS_STRIDE * 2 + ks * 32);
                mma16816(acc[2 * nss],     Af[ks][0], Af[ks][1], Af[ks][2], Af[ks][3], B0, B1);
                mma16816(acc[2 * nss + 1], Af[ks][0], Af[ks][1], Af[ks][2], Af[ks][3], B2, B3);
            }
        }

        const int colbase = c0g + h * 64;
        #pragma unroll
        for (int s = 0; s < 8; s++) {
            const int col = colbase + s * 8 + cp;
            const size_t row0 = (size_t)(a0 + m0 + r);
            *(__half2*)&g_Yh[row0 * YSTRIDE + col]       = __floats2half2_rn(acc[s][0], acc[s][1]);
            *(__half2*)&g_Yh[(row0 + 8) * YSTRIDE + col] = __floats2half2_rn(acc[s][2], acc[s][3]);
        }
    }
}

// ---------------------------------------------------------------------------
// Phase 2: half-warp per edge (R7 structure, validated 14.1us; stride updated).
// Lane lid handles output features 4*lid..4*lid+3.
// ---------------------------------------------------------------------------
__global__ void __launch_bounds__(256)
edge_kernel(const float* __restrict__ bond,
            const int* __restrict__ pair,
            float* __restrict__ out)
{
    const int warp = blockIdx.x * 8 + (threadIdx.x >> 5);
    const int half = (threadIdx.x >> 4) & 1;
    const int lid  = threadIdx.x & 15;
    const int e = warp * 2 + half;

    const int2 pr = ((const int2*)pair)[e];
    const int dst = pr.x;
    const int src = pr.y;

    const float4* __restrict__ bp = (const float4*)(bond + (size_t)e * 16);
    const float4 q0 = __ldg(bp + 0);
    const float4 q1 = __ldg(bp + 1);
    const float4 q2 = __ldg(bp + 2);
    const float4 q3 = __ldg(bp + 3);
    const float bk[16] = {q0.x, q0.y, q0.z, q0.w,
                          q1.x, q1.y, q1.z, q1.w,
                          q2.x, q2.y, q2.z, q2.w,
                          q3.x, q3.y, q3.z, q3.w};

    const __half* __restrict__ y = g_Yh + (size_t)src * YSTRIDE + 4 * lid;

    float m0, m1, m2, m3;
    {
        const uint2 v = *(const uint2*)(y + 1024);
        const float2 flo = __half22float2(*(const __half2*)&v.x);
        const float2 fhi = __half22float2(*(const __half2*)&v.y);
        m0 = flo.x; m1 = flo.y; m2 = fhi.x; m3 = fhi.y;
    }

    #pragma unroll
    for (int k = 0; k < 16; k++) {
        const uint2 v = *(const uint2*)(y + k * 64);
        const float2 flo = __half22float2(*(const __half2*)&v.x);
        const float2 fhi = __half22float2(*(const __half2*)&v.y);
        const float b = bk[k];
        m0 = fmaf(b, flo.x, m0);
        m1 = fmaf(b, flo.y, m1);
        m2 = fmaf(b, fhi.x, m2);
        m3 = fmaf(b, fhi.y, m3);
    }

    float* o = out + (size_t)dst * 64 + 4 * lid;
    asm volatile("red.global.add.v4.f32 [%0], {%1, %2, %3, %4};"
                 :: "l"(o), "f"(m0), "f"(m1), "f"(m2), "f"(m3)
                 : "memory");
}

extern "C" void kernel_launch(void* const* d_in, const int* in_sizes, int n_in,
                              void* d_out, int out_size)
{
    const float* atom = (const float*)d_in[0];      // [4480, 64]
    const float* bond = (const float*)d_in[1];      // [65536, 16]
    const int*   pair = (const int*)d_in[2];        // [65536, 2] int32
    const float* kern = (const float*)d_in[3];      // [16, 4096]
    const float* bias = (const float*)d_in[4];      // [4096]
    float*       out  = (float*)d_out;              // [4480, 64]

    (void)in_sizes; (void)n_in; (void)out_size;

    dim3 grid1(NUM_SEGMENTS / 128, 9);  // (35, 9); y==0 blocks zero `out`
    proj_kernel<<<grid1, 256>>>(atom, kern, bias, out);

    edge_kernel<<<N_EDGES / 16, 256>>>(bond, pair, out);
}